// round 15
// baseline (speedup 1.0000x reference)
#include <cuda_runtime.h>
#include <math.h>
#include <stdint.h>

static constexpr int NN  = 20000;
static constexpr int EE  = 320000;
static constexpr int GG  = 256;
static constexpr int INF = 128;
static constexpr int DD  = 256;
static constexpr int PP  = 16;
#define EPSV 1e-7f
#define TEMPV 0.2f

static constexpr size_t O_KL  = 0;
static constexpr size_t O_NCE = 1;
static constexpr size_t O_SIM = 2;
static constexpr size_t O_NB  = O_SIM + (size_t)GG*PP;
static constexpr size_t O_EB  = O_NB  + NN;
static constexpr size_t O_DS  = O_EB  + EE;
static constexpr size_t O_SE  = O_DS  + (size_t)GG*GG;
static constexpr size_t O_NE  = O_SE  + (size_t)GG*DD;
// d_out at O_SE/O_NE is only 8-byte aligned: NEVER 16B access into d_out.

static constexpr int SCAN_B = (NN + 255) / 256;   // 79

// -------- device scratch --------
__device__ __align__(16) float g_agg[(size_t)NN*DD];
__device__ __align__(16) float g_h1 [(size_t)NN*DD];
__device__ __align__(16) float g_h2 [(size_t)NN*DD];
__device__ __align__(16) float g_hid[(size_t)NN*DD];
__device__ float g_pnorm[PP];
__device__ float g_gnorm[GG];
__device__ float g_contrib[PP*DD];
__device__ float g_nb[NN];
__device__ float g_nprob[NN];
__device__ int   g_assign[GG];
__device__ float g_acc[4];
__device__ int   g_done;
__device__ int g_cnt[NN];
__device__ int g_ptr[NN + 1];
__device__ int g_cursor[NN];
__device__ int g_csrc[EE];
__device__ int g_gstart[GG + 1];
__device__ int g_bsum[SCAN_B];

__device__ __forceinline__ float warp_sum(float v) {
#pragma unroll
    for (int o = 16; o > 0; o >>= 1) v += __shfl_down_sync(0xffffffffu, v, o);
    return __shfl_sync(0xffffffffu, v, 0);
}

__device__ __forceinline__ void block_atomic_add(float v, float* slot) {
    __shared__ float sh[8];
#pragma unroll
    for (int o = 16; o > 0; o >>= 1) v += __shfl_down_sync(0xffffffffu, v, o);
    if ((threadIdx.x & 31) == 0) sh[threadIdx.x >> 5] = v;
    __syncthreads();
    if (threadIdx.x == 0) {
        float t = 0.f;
        int nw = blockDim.x >> 5;
        for (int q = 0; q < nw; q++) t += sh[q];
        atomicAdd(slot, t);
    }
}

// -------- init: zero scratch + gstart --------
__global__ void init_k(int* __restrict__ cnt, int* __restrict__ cursor,
                       float* __restrict__ nprob, float* __restrict__ acc,
                       int* __restrict__ done,
                       const int* __restrict__ batch, int* __restrict__ gs) {
    cudaGridDependencySynchronize();
    int b = blockIdx.x, t = threadIdx.x;
    if (b < SCAN_B) {
        int i = b * 256 + t;
        if (i < NN) { cnt[i] = 0; cursor[i] = 0; nprob[i] = 0.f; }
        if (b == 0) {
            if (t < 4) acc[t] = 0.f;
            if (t == 4) *done = 0;
        }
    } else {
        int g = (b - SCAN_B) * 256 + t;
        if (g > GG) return;
        if (g == GG) { gs[GG] = NN; return; }
        int lo = 0, hi = NN;
        while (lo < hi) { int mid = (lo + hi) >> 1; if (batch[mid] < g) lo = mid + 1; else hi = mid; }
        gs[g] = lo;
    }
}

// -------- CSR build --------
__global__ void hist_k(const int* __restrict__ dst, int* __restrict__ cnt) {
    cudaGridDependencySynchronize();
    int e = blockIdx.x * blockDim.x + threadIdx.x;
    if (e < EE) atomicAdd(&cnt[dst[e]], 1);
}

__global__ void scan1_k(const int* __restrict__ cnt, int* __restrict__ ptr,
                        int* __restrict__ bsum) {
    cudaGridDependencySynchronize();
    int i = blockIdx.x * 256 + threadIdx.x;
    int lane = threadIdx.x & 31, w = threadIdx.x >> 5;
    int v = (i < NN) ? cnt[i] : 0;
    int s = v;
#pragma unroll
    for (int o = 1; o < 32; o <<= 1) {
        int t = __shfl_up_sync(0xffffffffu, s, o);
        if (lane >= o) s += t;
    }
    __shared__ int ws[8];
    if (lane == 31) ws[w] = s;
    __syncthreads();
    if (threadIdx.x < 8) {
        int t = ws[threadIdx.x];
#pragma unroll
        for (int o = 1; o < 8; o <<= 1) {
            int u = __shfl_up_sync(0xffu, t, o);
            if ((int)threadIdx.x >= o) t += u;
        }
        ws[threadIdx.x] = t;
    }
    __syncthreads();
    int excl = s - v + (w ? ws[w - 1] : 0);
    if (i < NN) ptr[i] = excl;
    if (threadIdx.x == 255) bsum[blockIdx.x] = excl + v;
}

__global__ void scan2_k(int* __restrict__ ptr, const int* __restrict__ bsum) {
    cudaGridDependencySynchronize();
    int b = blockIdx.x;
    int partial = 0;
    for (int j = threadIdx.x; j < b; j += 256) partial += bsum[j];
    __shared__ int sh[8];
    int lane = threadIdx.x & 31, w = threadIdx.x >> 5;
#pragma unroll
    for (int o = 16; o > 0; o >>= 1) partial += __shfl_down_sync(0xffffffffu, partial, o);
    if (lane == 0) sh[w] = partial;
    __syncthreads();
    __shared__ int off;
    if (threadIdx.x == 0) {
        int t = 0;
#pragma unroll
        for (int q = 0; q < 8; q++) t += sh[q];
        off = t;
    }
    __syncthreads();
    int i = b * 256 + threadIdx.x;
    if (i < NN) ptr[i] += off;
    if (b == gridDim.x - 1 && threadIdx.x == 0) ptr[NN] = off + bsum[b];
}

__global__ void fill_k(const int* __restrict__ src, const int* __restrict__ dst,
                       const int* __restrict__ ptr, int* __restrict__ cursor,
                       int* __restrict__ csrc) {
    cudaGridDependencySynchronize();
    int e = blockIdx.x * blockDim.x + threadIdx.x;
    if (e >= EE) return;
    int d = dst[e];
    int s = atomicAdd(&cursor[d], 1);
    csrc[ptr[d] + s] = src[e];
}

// -------- prototype prep --------
__global__ void protprep_k(const float* __restrict__ proto, const float* __restrict__ Wm1,
                           float* __restrict__ contrib, float* __restrict__ pnorm) {
    cudaGridDependencySynchronize();
    __shared__ float pr[DD];
    int p = blockIdx.x, tid = threadIdx.x;
    float e = proto[(size_t)p * DD + tid];
    pr[tid] = e;
    __syncthreads();
    float a = 0.f;
    for (int k = 0; k < DD; k++) a += pr[k] * Wm1[(size_t)(DD + k) * DD + tid];
    contrib[(size_t)p * DD + tid] = a;
    float sq = e * e;
    __shared__ float sh[8];
    int lane = tid & 31, w = tid >> 5;
#pragma unroll
    for (int o = 16; o > 0; o >>= 1) sq += __shfl_down_sync(0xffffffffu, sq, o);
    if (lane == 0) sh[w] = sq;
    __syncthreads();
    if (tid == 0) {
        float t = 0.f;
#pragma unroll
        for (int q = 0; q < 8; q++) t += sh[q];
        float n = sqrtf(t);
        if (n == 0.f) n = EPSV;
        pnorm[p] = n;
    }
}

// -------- gather: 2 edge-groups per node + smem combine (pool-proven pattern) --------
// MODE 0: agg = h[n] + sum h[s]
// MODE 1: agg = nb[n]*(h[n] + sum nb[s]^2 h[s])
// MODE 2: agg = h[n] + nb[n]*sum nb[s] h[s]
template <int D, int MODE>
__global__ void gather_k(const float* __restrict__ h, const int* __restrict__ ptr,
                         const int* __restrict__ csrc, const float* __restrict__ nb,
                         float* __restrict__ agg) {
    cudaGridDependencySynchronize();
    constexpr int TPN = D / 4;             // threads per group (32 or 64)
    constexpr int NPB = 256 / (2 * TPN);   // nodes per block (4 or 2)
    __shared__ float part[NPB][TPN * 4];
    int idx  = threadIdx.x / (2 * TPN);    // node slot in block
    int rem  = threadIdx.x % (2 * TPN);
    int grp  = rem / TPN;                  // 0 or 1
    int lane = rem % TPN;
    int node = blockIdx.x * NPB + idx;
    bool ok = node < NN;
    int b = 0, e = 0;
    if (ok) { b = ptr[node]; e = ptr[node + 1]; }
    float4 acc = make_float4(0.f, 0.f, 0.f, 0.f);
    // group grp handles edge positions b+grp, b+grp+2, ... ; 2 issued per iter
    for (int i = b + grp; i < e; i += 4) {
        int s0 = csrc[i];
        bool has1 = (i + 2 < e);
        int s1 = has1 ? csrc[i + 2] : s0;
        float w0 = 1.f, w1 = has1 ? 1.f : 0.f;
        if (MODE == 1) { w0 = nb[s0]; w0 *= w0; float t = nb[s1]; w1 *= t * t; }
        if (MODE == 2) { w0 = nb[s0]; w1 *= nb[s1]; }
        float4 v0 = *(const float4*)(h + (size_t)s0 * D + lane * 4);
        float4 v1 = *(const float4*)(h + (size_t)s1 * D + lane * 4);
        acc.x += w0 * v0.x + w1 * v1.x;
        acc.y += w0 * v0.y + w1 * v1.y;
        acc.z += w0 * v0.z + w1 * v1.z;
        acc.w += w0 * v0.w + w1 * v1.w;
    }
    if (grp == 1) *(float4*)&part[idx][lane * 4] = acc;
    __syncthreads();
    if (grp == 0 && ok) {
        float4 p1 = *(float4*)&part[idx][lane * 4];
        acc.x += p1.x; acc.y += p1.y; acc.z += p1.z; acc.w += p1.w;
        float4 hv = *(const float4*)(h + (size_t)node * D + lane * 4);
        float4 r;
        if (MODE == 0) {
            r = make_float4(hv.x + acc.x, hv.y + acc.y, hv.z + acc.z, hv.w + acc.w);
        } else if (MODE == 1) {
            float a = nb[node];
            r = make_float4(a * (hv.x + acc.x), a * (hv.y + acc.y),
                            a * (hv.z + acc.z), a * (hv.w + acc.w));
        } else {
            float a = nb[node];
            r = make_float4(hv.x + a * acc.x, hv.y + a * acc.y,
                            hv.z + a * acc.z, hv.w + a * acc.w);
        }
        *(float4*)(agg + (size_t)node * D + lane * 4) = r;
    }
}

// -------- pool + prototype argmax (pass 1): 256 threads, 4-way node parallel --------
__global__ void pool_argmax_k(const float* __restrict__ h, const int* __restrict__ gs,
                              const float* __restrict__ proto, const float* __restrict__ pnorm,
                              int* __restrict__ assign) {
    cudaGridDependencySynchronize();
    __shared__ float part[4][DD];
    int g = blockIdx.x, t = threadIdx.x;
    int grp = t >> 6, l = t & 63;
    int b = gs[g], e = gs[g + 1];
    float4 acc = make_float4(0.f, 0.f, 0.f, 0.f);
    for (int n = b + grp; n < e; n += 4) {
        float4 v = *(const float4*)(h + (size_t)n * DD + l * 4);
        acc.x += v.x; acc.y += v.y; acc.z += v.z; acc.w += v.w;
    }
    *(float4*)&part[grp][l * 4] = acc;
    __syncthreads();
    if (t < 64) {
        float4 a0 = *(float4*)&part[0][t * 4];
        float4 a1 = *(float4*)&part[1][t * 4];
        float4 a2 = *(float4*)&part[2][t * 4];
        float4 a3 = *(float4*)&part[3][t * 4];
        float4 r = make_float4(a0.x + a1.x + a2.x + a3.x, a0.y + a1.y + a2.y + a3.y,
                               a0.z + a1.z + a2.z + a3.z, a0.w + a1.w + a2.w + a3.w);
        *(float4*)&part[0][t * 4] = r;
    }
    __syncthreads();
    if (t < 32) {
        int lane = t;
        float ge[8];
        float ns = 0.f;
#pragma unroll
        for (int q = 0; q < 8; q++) { ge[q] = part[0][lane + q * 32]; ns += ge[q] * ge[q]; }
        ns = warp_sum(ns);
        float nrm = sqrtf(ns);
        if (nrm == 0.f) nrm = EPSV;
        float best = -1e30f;
        int bi = 0;
        for (int p = 0; p < PP; p++) {
            float d = 0.f;
#pragma unroll
            for (int q = 0; q < 8; q++) d += ge[q] * proto[(size_t)p * DD + lane + q * 32];
            d = warp_sum(d);
            float sim = d / (nrm * pnorm[p]);
            if (sim > best) { best = sim; bi = p; }
        }
        if (lane == 0) assign[g] = bi;
    }
}

// -------- pool + row norm (pass 2): 256 threads, 4-way node parallel --------
__global__ void pool_norm_k(const float* __restrict__ h, const int* __restrict__ gs,
                            float* __restrict__ gout, float* __restrict__ gnorm) {
    cudaGridDependencySynchronize();
    __shared__ float part[4][DD];
    int g = blockIdx.x, t = threadIdx.x;
    int grp = t >> 6, l = t & 63;
    int b = gs[g], e = gs[g + 1];
    float4 acc = make_float4(0.f, 0.f, 0.f, 0.f);
    for (int n = b + grp; n < e; n += 4) {
        float4 v = *(const float4*)(h + (size_t)n * DD + l * 4);
        acc.x += v.x; acc.y += v.y; acc.z += v.z; acc.w += v.w;
    }
    *(float4*)&part[grp][l * 4] = acc;
    __syncthreads();
    if (t < 64) {
        float4 a0 = *(float4*)&part[0][t * 4];
        float4 a1 = *(float4*)&part[1][t * 4];
        float4 a2 = *(float4*)&part[2][t * 4];
        float4 a3 = *(float4*)&part[3][t * 4];
        float4 r = make_float4(a0.x + a1.x + a2.x + a3.x, a0.y + a1.y + a2.y + a3.y,
                               a0.z + a1.z + a2.z + a3.z, a0.w + a1.w + a2.w + a3.w);
        float* o = gout + (size_t)g * DD + t * 4;
        *(float2*)(o)     = make_float2(r.x, r.y);   // d_out 8B-aligned: float2 only
        *(float2*)(o + 2) = make_float2(r.z, r.w);
        *(float4*)&part[0][t * 4] = r;
    }
    __syncthreads();
    if (t < 32) {
        float sq = 0.f;
#pragma unroll
        for (int q = 0; q < 8; q++) {
            float v = part[0][t + q * 32];
            sq += v * v;
        }
        sq = warp_sum(sq);
        if (t == 0) {
            float n = sqrtf(sq);
            if (n == 0.f) n = EPSV;
            gnorm[g] = n;
        }
    }
}

// ======== TF32 tensor-core GEMM (128x128x16, 8 warps, m16n8k8) ========
__device__ __forceinline__ uint32_t f2tf(float f) {
    uint32_t r;
    asm("cvt.rna.tf32.f32 %0, %1;" : "=r"(r) : "f"(f));
    return r;
}
__device__ __forceinline__ void mma8(float* c, uint32_t a0, uint32_t a1, uint32_t a2,
                                     uint32_t a3, uint32_t b0, uint32_t b1) {
    asm volatile(
        "mma.sync.aligned.m16n8k8.row.col.f32.tf32.tf32.f32 "
        "{%0,%1,%2,%3}, {%4,%5,%6,%7}, {%8,%9}, {%0,%1,%2,%3};"
        : "+f"(c[0]), "+f"(c[1]), "+f"(c[2]), "+f"(c[3])
        : "r"(a0), "r"(a1), "r"(a2), "r"(a3), "r"(b0), "r"(b1));
}

#define TBM 128
#define TBN 128
#define TBK 16
#define ASTR 20
#define WSTR 136

__global__ __launch_bounds__(256, 2)
void gemm_tc_k(const float* __restrict__ A, const float* __restrict__ W,
               const float* __restrict__ bias, float* __restrict__ C,
               int M, int K, int Nout,
               const float* __restrict__ rowExtra, const int* __restrict__ batv,
               const int* __restrict__ assignv, float* __restrict__ C2,
               float* __restrict__ nprob, const float* __restrict__ Wm2v) {
    cudaGridDependencySynchronize();
    __shared__ uint32_t As[2][TBM * ASTR];
    __shared__ uint32_t Ws[2][TBK * WSTR];
    int bm = blockIdx.y * TBM, bn = blockIdx.x * TBN;
    int tid = threadIdx.x;
    int wid = tid >> 5, lane = tid & 31;
    int g = lane >> 2, tg = lane & 3;
    int wm = (wid & 1) * 64;
    int wn = (wid >> 1) * 32;

    int arow = tid >> 2;
    int acol = (tid & 3) * 4;
    int wrow = tid >> 5;
    int wcol = (tid & 31) * 4;
    int gr0 = bm + arow, gr1 = bm + arow + 64;

    const int kTiles = K / TBK;
    float4 a0g, a1g, w0g, w1g;

    {
        const float* Ab = A + acol;
        a0g = (gr0 < M) ? *(const float4*)(Ab + (size_t)gr0 * K) : make_float4(0,0,0,0);
        a1g = (gr1 < M) ? *(const float4*)(Ab + (size_t)gr1 * K) : make_float4(0,0,0,0);
        const float* Wb = W + (size_t)wrow * Nout + bn + wcol;
        w0g = *(const float4*)(Wb);
        w1g = *(const float4*)(Wb + (size_t)8 * Nout);
        uint4 p;
        p.x = f2tf(a0g.x); p.y = f2tf(a0g.y); p.z = f2tf(a0g.z); p.w = f2tf(a0g.w);
        *(uint4*)&As[0][arow * ASTR + acol] = p;
        p.x = f2tf(a1g.x); p.y = f2tf(a1g.y); p.z = f2tf(a1g.z); p.w = f2tf(a1g.w);
        *(uint4*)&As[0][(arow + 64) * ASTR + acol] = p;
        p.x = f2tf(w0g.x); p.y = f2tf(w0g.y); p.z = f2tf(w0g.z); p.w = f2tf(w0g.w);
        *(uint4*)&Ws[0][wrow * WSTR + wcol] = p;
        p.x = f2tf(w1g.x); p.y = f2tf(w1g.y); p.z = f2tf(w1g.z); p.w = f2tf(w1g.w);
        *(uint4*)&Ws[0][(wrow + 8) * WSTR + wcol] = p;
    }
    __syncthreads();

    float acc[4][4][4];
#pragma unroll
    for (int a = 0; a < 4; a++)
#pragma unroll
        for (int b = 0; b < 4; b++)
#pragma unroll
            for (int c = 0; c < 4; c++) acc[a][b][c] = 0.f;

    for (int t = 0; t < kTiles; t++) {
        int buf = t & 1;
        if (t + 1 < kTiles) {
            const float* Ab = A + (t + 1) * TBK + acol;
            a0g = (gr0 < M) ? *(const float4*)(Ab + (size_t)gr0 * K) : make_float4(0,0,0,0);
            a1g = (gr1 < M) ? *(const float4*)(Ab + (size_t)gr1 * K) : make_float4(0,0,0,0);
            const float* Wb = W + (size_t)((t + 1) * TBK + wrow) * Nout + bn + wcol;
            w0g = *(const float4*)(Wb);
            w1g = *(const float4*)(Wb + (size_t)8 * Nout);
        }
#pragma unroll
        for (int ks = 0; ks < TBK; ks += 8) {
            uint32_t af[4][4], bf[4][2];
#pragma unroll
            for (int mt = 0; mt < 4; mt++) {
                int r = wm + mt * 16 + g;
                af[mt][0] = As[buf][r * ASTR + ks + tg];
                af[mt][1] = As[buf][(r + 8) * ASTR + ks + tg];
                af[mt][2] = As[buf][r * ASTR + ks + tg + 4];
                af[mt][3] = As[buf][(r + 8) * ASTR + ks + tg + 4];
            }
#pragma unroll
            for (int nt = 0; nt < 4; nt++) {
                int c = wn + nt * 8 + g;
                bf[nt][0] = Ws[buf][(ks + tg) * WSTR + c];
                bf[nt][1] = Ws[buf][(ks + tg + 4) * WSTR + c];
            }
#pragma unroll
            for (int mt = 0; mt < 4; mt++)
#pragma unroll
                for (int nt = 0; nt < 4; nt++)
                    mma8(acc[mt][nt], af[mt][0], af[mt][1], af[mt][2], af[mt][3],
                         bf[nt][0], bf[nt][1]);
        }
        if (t + 1 < kTiles) {
            int nb_ = buf ^ 1;
            uint4 p;
            p.x = f2tf(a0g.x); p.y = f2tf(a0g.y); p.z = f2tf(a0g.z); p.w = f2tf(a0g.w);
            *(uint4*)&As[nb_][arow * ASTR + acol] = p;
            p.x = f2tf(a1g.x); p.y = f2tf(a1g.y); p.z = f2tf(a1g.z); p.w = f2tf(a1g.w);
            *(uint4*)&As[nb_][(arow + 64) * ASTR + acol] = p;
            p.x = f2tf(w0g.x); p.y = f2tf(w0g.y); p.z = f2tf(w0g.z); p.w = f2tf(w0g.w);
            *(uint4*)&Ws[nb_][wrow * WSTR + wcol] = p;
            p.x = f2tf(w1g.x); p.y = f2tf(w1g.y); p.z = f2tf(w1g.z); p.w = f2tf(w1g.w);
            *(uint4*)&Ws[nb_][(wrow + 8) * WSTR + wcol] = p;
        }
        __syncthreads();
    }

#pragma unroll
    for (int mt = 0; mt < 4; mt++) {
#pragma unroll
        for (int half = 0; half < 2; half++) {
            int row = bm + wm + mt * 16 + g + half * 8;
            bool rok = row < M;
            int rsafe = rok ? row : 0;
            const float* ex = rowExtra ? rowExtra + (size_t)assignv[batv[rsafe]] * Nout : nullptr;
            float part = 0.f;
#pragma unroll
            for (int nt = 0; nt < 4; nt++) {
                int col = bn + wn + nt * 8 + tg * 2;
                float v0 = acc[mt][nt][half * 2 + 0] + bias[col];
                float v1 = acc[mt][nt][half * 2 + 1] + bias[col + 1];
                if (ex) { v0 += ex[col]; v1 += ex[col + 1]; }
                v0 = fmaxf(v0, 0.f); v1 = fmaxf(v1, 0.f);
                if (rok) {
                    if (C)  *(float2*)(C  + (size_t)row * Nout + col) = make_float2(v0, v1);
                    if (C2) *(float2*)(C2 + (size_t)row * Nout + col) = make_float2(v0, v1);
                }
                if (nprob) part += v0 * Wm2v[col] + v1 * Wm2v[col + 1];
            }
            if (nprob) {
                part += __shfl_down_sync(0xffffffffu, part, 2);
                part += __shfl_down_sync(0xffffffffu, part, 1);
                if (tg == 0 && rok) atomicAdd(&nprob[row], part);
            }
        }
    }
}

// -------- sigmoid + node KL --------
__global__ void nprob_sig_k(const float* __restrict__ nprob, const float* __restrict__ bm2,
                            float* __restrict__ nb, float* __restrict__ nbout,
                            float* __restrict__ acc) {
    cudaGridDependencySynchronize();
    int i = blockIdx.x * blockDim.x + threadIdx.x;
    float term = 0.f;
    if (i < NN) {
        float s = 1.f / (1.f + expf(-(nprob[i] + bm2[0])));
        nb[i] = s; nbout[i] = s;
        term = s * logf(s / 0.5f + EPSV)
             + (1.f - s) * logf((1.f - s) / (1.f - 0.5f + EPSV) + EPSV);
    }
    block_atomic_add(term, acc);
}

// -------- edge bern + edge KL --------
__global__ void edgebern_k(const float* __restrict__ nb, const int* __restrict__ src,
                           const int* __restrict__ dst, float* __restrict__ out,
                           float* __restrict__ acc) {
    cudaGridDependencySynchronize();
    int i = blockIdx.x * blockDim.x + threadIdx.x;
    float term = 0.f;
    if (i < EE) {
        float v = nb[src[i]] * nb[dst[i]];
        out[i] = v;
        term = v * logf(v / 0.25f + EPSV)
             + (1.f - v) * logf((1.f - v) / (1.f - 0.25f + EPSV) + EPSV);
    }
    block_atomic_add(term, acc + 1);
}

// -------- fused similarity/NCE + data_sim + finalize --------
__global__ void simdata_k(const float* __restrict__ semb, const float* __restrict__ gnorm,
                          const float* __restrict__ proto, const float* __restrict__ pnorm,
                          float* __restrict__ simout, float* __restrict__ dsout,
                          float* __restrict__ acc, int* __restrict__ done,
                          float* __restrict__ out) {
    cudaGridDependencySynchronize();
    __shared__ float ri[DD];
    int i = blockIdx.x, tid = threadIdx.x, lane = tid & 31, w = tid >> 5;
    ri[tid] = semb[(size_t)i * DD + tid];
    __syncthreads();
    float ni = gnorm[i];
    if (tid < 32) {
        float ge[8];
#pragma unroll
        for (int q = 0; q < 8; q++) ge[q] = ri[lane + q * 32];
        float best = -1e30f, pos = 0.f, sum = 0.f;
        for (int p = 0; p < PP; p++) {
            float d = 0.f;
#pragma unroll
            for (int q = 0; q < 8; q++) d += ge[q] * proto[(size_t)p * DD + lane + q * 32];
            d = warp_sum(d);
            float sim = d / (ni * pnorm[p]);
            if (lane == 0) simout[(size_t)i * PP + p] = sim;
            float se = expf(sim / TEMPV);
            sum += se;
            if (sim > best) { best = sim; pos = se; }
        }
        if (lane == 0) atomicAdd(&acc[2], -logf(pos / (sum - pos)));
    }
    for (int j = w; j < GG; j += 8) {
        float d = 0.f;
#pragma unroll
        for (int q = 0; q < 8; q++) {
            int c = lane + q * 32;
            d += ri[c] * semb[(size_t)j * DD + c];
        }
        d = warp_sum(d);
        if (lane == 0) dsout[(size_t)i * GG + j] = d / (ni * gnorm[j]);
    }
    __syncthreads();
    if (tid == 0) {
        __threadfence();
        int t = atomicAdd(done, 1);
        if (t == GG - 1) {
            __threadfence();
            out[O_KL]  = acc[0] / (float)NN + acc[1] / (float)EE;
            out[O_NCE] = acc[2] / (float)GG;
        }
    }
}

// -------- PDL launch helper --------
template <typename... Args>
static inline void launch_pdl(void (*kern)(Args...), dim3 grid, dim3 block, Args... args) {
    cudaLaunchConfig_t cfg = {};
    cfg.gridDim = grid;
    cfg.blockDim = block;
    cfg.dynamicSmemBytes = 0;
    cudaLaunchAttribute attr[1];
    attr[0].id = cudaLaunchAttributeProgrammaticStreamSerialization;
    attr[0].val.programmaticStreamSerializationAllowed = 1;
    cfg.attrs = attr;
    cfg.numAttrs = 1;
    cudaLaunchKernelEx(&cfg, kern, args...);
}

// =====================================================================
extern "C" void kernel_launch(void* const* d_in, const int* in_sizes, int n_in,
                              void* d_out, int out_size) {
    const float* x    = (const float*)d_in[0];
    const int*   ei   = (const int*)d_in[1];
    const int*   bat  = (const int*)d_in[2];
    const float* W1   = (const float*)d_in[3];
    const float* b1   = (const float*)d_in[4];
    const float* W2   = (const float*)d_in[5];
    const float* b2   = (const float*)d_in[6];
    const float* Wm1  = (const float*)d_in[7];
    const float* bm1  = (const float*)d_in[8];
    const float* Wm2  = (const float*)d_in[9];
    const float* bm2  = (const float*)d_in[10];
    const float* prot = (const float*)d_in[11];
    float* out = (float*)d_out;

    const int* src = ei;
    const int* dst = ei + EE;

    float *agg, *h1, *h2, *hid, *pnorm, *gnorm, *contrib, *nb, *nprob, *acc;
    int *assign, *cnt, *ptr, *cursor, *csrc, *gstart, *bsum, *done;
    cudaGetSymbolAddress((void**)&agg, g_agg);
    cudaGetSymbolAddress((void**)&h1, g_h1);
    cudaGetSymbolAddress((void**)&h2, g_h2);
    cudaGetSymbolAddress((void**)&hid, g_hid);
    cudaGetSymbolAddress((void**)&pnorm, g_pnorm);
    cudaGetSymbolAddress((void**)&gnorm, g_gnorm);
    cudaGetSymbolAddress((void**)&contrib, g_contrib);
    cudaGetSymbolAddress((void**)&nb, g_nb);
    cudaGetSymbolAddress((void**)&nprob, g_nprob);
    cudaGetSymbolAddress((void**)&acc, g_acc);
    cudaGetSymbolAddress((void**)&assign, g_assign);
    cudaGetSymbolAddress((void**)&cnt, g_cnt);
    cudaGetSymbolAddress((void**)&ptr, g_ptr);
    cudaGetSymbolAddress((void**)&cursor, g_cursor);
    cudaGetSymbolAddress((void**)&csrc, g_csrc);
    cudaGetSymbolAddress((void**)&gstart, g_gstart);
    cudaGetSymbolAddress((void**)&bsum, g_bsum);
    cudaGetSymbolAddress((void**)&done, g_done);

    auto blks = [](long n, int t) { return (int)((n + t - 1) / t); };

    // ---- init + CSR build ----
    launch_pdl(init_k, dim3(SCAN_B + 2), dim3(256),
               cnt, cursor, nprob, acc, done, bat, gstart);
    launch_pdl(hist_k, dim3(blks(EE, 256)), dim3(256), dst, cnt);
    launch_pdl(scan1_k, dim3(SCAN_B), dim3(256), (const int*)cnt, ptr, bsum);
    launch_pdl(scan2_k, dim3(SCAN_B), dim3(256), ptr, (const int*)bsum);
    launch_pdl(fill_k, dim3(blks(EE, 256)), dim3(256),
               src, dst, (const int*)ptr, cursor, csrc);
    launch_pdl(protprep_k, dim3(PP), dim3(DD), prot, Wm1, contrib, pnorm);

    dim3 gg(DD / TBN, (NN + TBM - 1) / TBM);

    // ---- pass 1 ----
    launch_pdl(gather_k<INF, 0>, dim3(blks(NN, 4)), dim3(256),
               x, (const int*)ptr, (const int*)csrc, (const float*)nullptr, agg);
    launch_pdl(gemm_tc_k, gg, dim3(256),
               (const float*)agg, W1, b1, h1, NN, INF, DD,
               (const float*)nullptr, (const int*)nullptr, (const int*)nullptr,
               (float*)nullptr, (float*)nullptr, (const float*)nullptr);
    launch_pdl(gather_k<DD, 0>, dim3(blks(NN, 2)), dim3(256),
               (const float*)h1, (const int*)ptr, (const int*)csrc,
               (const float*)nullptr, agg);
    launch_pdl(gemm_tc_k, gg, dim3(256),
               (const float*)agg, W2, b2, h2, NN, DD, DD,
               (const float*)nullptr, (const int*)nullptr, (const int*)nullptr,
               out + O_NE, (float*)nullptr, (const float*)nullptr);
    launch_pdl(pool_argmax_k, dim3(GG), dim3(256),
               (const float*)h2, (const int*)gstart, prot, (const float*)pnorm, assign);

    // ---- MLP (nodeprob dot fused into GEMM epilogue; hid not written) ----
    launch_pdl(gemm_tc_k, gg, dim3(256),
               (const float*)h2, Wm1, bm1, (float*)nullptr, NN, DD, DD,
               (const float*)contrib, bat, (const int*)assign,
               (float*)nullptr, nprob, Wm2);
    launch_pdl(nprob_sig_k, dim3(SCAN_B), dim3(256),
               (const float*)nprob, bm2, nb, out + O_NB, acc);
    launch_pdl(edgebern_k, dim3(blks(EE, 256)), dim3(256),
               (const float*)nb, src, dst, out + O_EB, acc);

    // ---- pass 2 ----
    launch_pdl(gather_k<INF, 1>, dim3(blks(NN, 4)), dim3(256),
               x, (const int*)ptr, (const int*)csrc, (const float*)nb, agg);
    launch_pdl(gemm_tc_k, gg, dim3(256),
               (const float*)agg, W1, b1, h1, NN, INF, DD,
               (const float*)nullptr, (const int*)nullptr, (const int*)nullptr,
               (float*)nullptr, (float*)nullptr, (const float*)nullptr);
    launch_pdl(gather_k<DD, 2>, dim3(blks(NN, 2)), dim3(256),
               (const float*)h1, (const int*)ptr, (const int*)csrc,
               (const float*)nb, agg);
    launch_pdl(gemm_tc_k, gg, dim3(256),
               (const float*)agg, W2, b2, hid, NN, DD, DD,
               (const float*)nullptr, (const int*)nullptr, (const int*)nullptr,
               (float*)nullptr, (float*)nullptr, (const float*)nullptr);
    launch_pdl(pool_norm_k, dim3(GG), dim3(256),
               (const float*)hid, (const int*)gstart, out + O_SE, gnorm);

    // ---- similarity / NCE / data_sim / finalize ----
    launch_pdl(simdata_k, dim3(GG), dim3(DD),
               (const float*)(out + O_SE), (const float*)gnorm, prot,
               (const float*)pnorm, out + O_SIM, out + O_DS, acc, done, out);
}

// round 16
// speedup vs baseline: 1.0035x; 1.0035x over previous
#include <cuda_runtime.h>
#include <math.h>
#include <stdint.h>

static constexpr int NN  = 20000;
static constexpr int EE  = 320000;
static constexpr int GG  = 256;
static constexpr int INF = 128;
static constexpr int DD  = 256;
static constexpr int PP  = 16;
#define EPSV 1e-7f
#define TEMPV 0.2f

static constexpr size_t O_KL  = 0;
static constexpr size_t O_NCE = 1;
static constexpr size_t O_SIM = 2;
static constexpr size_t O_NB  = O_SIM + (size_t)GG*PP;
static constexpr size_t O_EB  = O_NB  + NN;
static constexpr size_t O_DS  = O_EB  + EE;
static constexpr size_t O_SE  = O_DS  + (size_t)GG*GG;
static constexpr size_t O_NE  = O_SE  + (size_t)GG*DD;
// d_out at O_SE/O_NE is only 8-byte aligned: NEVER 16B access into d_out.

static constexpr int SCAN_B = (NN + 255) / 256;   // 79
static constexpr int SE_B   = (GG * DD) / 256;    // 256 blocks to zero out+O_SE

// -------- device scratch --------
__device__ __align__(16) float g_agg[(size_t)NN*DD];
__device__ __align__(16) float g_h1 [(size_t)NN*DD];
__device__ __align__(16) float g_h2 [(size_t)NN*DD];
__device__ float g_pnorm[PP];
__device__ float g_gnorm[GG];
__device__ float g_contrib[PP*DD];
__device__ float g_nb[NN];
__device__ float g_nprob[NN];
__device__ int   g_assign[GG];
__device__ float g_acc[4];
__device__ int   g_done;
__device__ int g_cnt[NN];
__device__ int g_ptr[NN + 1];
__device__ int g_cursor[NN];
__device__ int g_csrc[EE];
__device__ int g_gstart[GG + 1];
__device__ int g_bsum[SCAN_B];

__device__ __forceinline__ float warp_sum(float v) {
#pragma unroll
    for (int o = 16; o > 0; o >>= 1) v += __shfl_down_sync(0xffffffffu, v, o);
    return __shfl_sync(0xffffffffu, v, 0);
}

__device__ __forceinline__ void block_atomic_add(float v, float* slot) {
    __shared__ float sh[8];
#pragma unroll
    for (int o = 16; o > 0; o >>= 1) v += __shfl_down_sync(0xffffffffu, v, o);
    if ((threadIdx.x & 31) == 0) sh[threadIdx.x >> 5] = v;
    __syncthreads();
    if (threadIdx.x == 0) {
        float t = 0.f;
        int nw = blockDim.x >> 5;
        for (int q = 0; q < nw; q++) t += sh[q];
        atomicAdd(slot, t);
    }
}

// -------- init: zero scratch + gstart + out[O_SE] region --------
__global__ void init_k(int* __restrict__ cnt, int* __restrict__ cursor,
                       float* __restrict__ nprob, float* __restrict__ acc,
                       int* __restrict__ done,
                       const int* __restrict__ batch, int* __restrict__ gs,
                       float* __restrict__ seout) {
    cudaGridDependencySynchronize();
    int b = blockIdx.x, t = threadIdx.x;
    if (b < SCAN_B) {
        int i = b * 256 + t;
        if (i < NN) { cnt[i] = 0; cursor[i] = 0; nprob[i] = 0.f; }
        if (b == 0) {
            if (t < 4) acc[t] = 0.f;
            if (t == 4) *done = 0;
        }
    } else if (b < SCAN_B + 2) {
        int g = (b - SCAN_B) * 256 + t;
        if (g > GG) return;
        if (g == GG) { gs[GG] = NN; return; }
        int lo = 0, hi = NN;
        while (lo < hi) { int mid = (lo + hi) >> 1; if (batch[mid] < g) lo = mid + 1; else hi = mid; }
        gs[g] = lo;
    } else {
        int i = (b - SCAN_B - 2) * 256 + t;
        seout[i] = 0.f;   // subgraph_embs accumulated by atomics in pass-2 GEMM
    }
}

// -------- CSR build --------
__global__ void hist_k(const int* __restrict__ dst, int* __restrict__ cnt) {
    cudaGridDependencySynchronize();
    int e = blockIdx.x * blockDim.x + threadIdx.x;
    if (e < EE) atomicAdd(&cnt[dst[e]], 1);
}

__global__ void scan1_k(const int* __restrict__ cnt, int* __restrict__ ptr,
                        int* __restrict__ bsum) {
    cudaGridDependencySynchronize();
    int i = blockIdx.x * 256 + threadIdx.x;
    int lane = threadIdx.x & 31, w = threadIdx.x >> 5;
    int v = (i < NN) ? cnt[i] : 0;
    int s = v;
#pragma unroll
    for (int o = 1; o < 32; o <<= 1) {
        int t = __shfl_up_sync(0xffffffffu, s, o);
        if (lane >= o) s += t;
    }
    __shared__ int ws[8];
    if (lane == 31) ws[w] = s;
    __syncthreads();
    if (threadIdx.x < 8) {
        int t = ws[threadIdx.x];
#pragma unroll
        for (int o = 1; o < 8; o <<= 1) {
            int u = __shfl_up_sync(0xffu, t, o);
            if ((int)threadIdx.x >= o) t += u;
        }
        ws[threadIdx.x] = t;
    }
    __syncthreads();
    int excl = s - v + (w ? ws[w - 1] : 0);
    if (i < NN) ptr[i] = excl;
    if (threadIdx.x == 255) bsum[blockIdx.x] = excl + v;
}

__global__ void scan2_k(int* __restrict__ ptr, const int* __restrict__ bsum) {
    cudaGridDependencySynchronize();
    int b = blockIdx.x;
    int partial = 0;
    for (int j = threadIdx.x; j < b; j += 256) partial += bsum[j];
    __shared__ int sh[8];
    int lane = threadIdx.x & 31, w = threadIdx.x >> 5;
#pragma unroll
    for (int o = 16; o > 0; o >>= 1) partial += __shfl_down_sync(0xffffffffu, partial, o);
    if (lane == 0) sh[w] = partial;
    __syncthreads();
    __shared__ int off;
    if (threadIdx.x == 0) {
        int t = 0;
#pragma unroll
        for (int q = 0; q < 8; q++) t += sh[q];
        off = t;
    }
    __syncthreads();
    int i = b * 256 + threadIdx.x;
    if (i < NN) ptr[i] += off;
    if (b == gridDim.x - 1 && threadIdx.x == 0) ptr[NN] = off + bsum[b];
}

__global__ void fill_k(const int* __restrict__ src, const int* __restrict__ dst,
                       const int* __restrict__ ptr, int* __restrict__ cursor,
                       int* __restrict__ csrc) {
    cudaGridDependencySynchronize();
    int e = blockIdx.x * blockDim.x + threadIdx.x;
    if (e >= EE) return;
    int d = dst[e];
    int s = atomicAdd(&cursor[d], 1);
    csrc[ptr[d] + s] = src[e];
}

// -------- prototype prep --------
__global__ void protprep_k(const float* __restrict__ proto, const float* __restrict__ Wm1,
                           float* __restrict__ contrib, float* __restrict__ pnorm) {
    cudaGridDependencySynchronize();
    __shared__ float pr[DD];
    int p = blockIdx.x, tid = threadIdx.x;
    float e = proto[(size_t)p * DD + tid];
    pr[tid] = e;
    __syncthreads();
    float a = 0.f;
    for (int k = 0; k < DD; k++) a += pr[k] * Wm1[(size_t)(DD + k) * DD + tid];
    contrib[(size_t)p * DD + tid] = a;
    float sq = e * e;
    __shared__ float sh[8];
    int lane = tid & 31, w = tid >> 5;
#pragma unroll
    for (int o = 16; o > 0; o >>= 1) sq += __shfl_down_sync(0xffffffffu, sq, o);
    if (lane == 0) sh[w] = sq;
    __syncthreads();
    if (tid == 0) {
        float t = 0.f;
#pragma unroll
        for (int q = 0; q < 8; q++) t += sh[q];
        float n = sqrtf(t);
        if (n == 0.f) n = EPSV;
        pnorm[p] = n;
    }
}

// -------- gather (fp32, 2-way edge unroll — r14 proven config) --------
template <int D, int MODE>
__global__ void gather_k(const float* __restrict__ h, const int* __restrict__ ptr,
                         const int* __restrict__ csrc, const float* __restrict__ nb,
                         float* __restrict__ agg) {
    cudaGridDependencySynchronize();
    constexpr int TPN = D / 4;
    constexpr int NPB = 256 / TPN;
    int node = blockIdx.x * NPB + threadIdx.x / TPN;
    int lane = threadIdx.x % TPN;
    if (node >= NN) return;
    int b = ptr[node], e = ptr[node + 1];
    float4 acc = make_float4(0.f, 0.f, 0.f, 0.f);
    int i = b;
    for (; i + 2 <= e; i += 2) {
        int s0 = csrc[i], s1 = csrc[i + 1];
        float w0 = 1.f, w1 = 1.f;
        if (MODE == 1) { w0 = nb[s0]; w0 *= w0; w1 = nb[s1]; w1 *= w1; }
        if (MODE == 2) { w0 = nb[s0]; w1 = nb[s1]; }
        float4 v0 = *(const float4*)(h + (size_t)s0 * D + lane * 4);
        float4 v1 = *(const float4*)(h + (size_t)s1 * D + lane * 4);
        acc.x += w0 * v0.x + w1 * v1.x;
        acc.y += w0 * v0.y + w1 * v1.y;
        acc.z += w0 * v0.z + w1 * v1.z;
        acc.w += w0 * v0.w + w1 * v1.w;
    }
    if (i < e) {
        int s0 = csrc[i];
        float w0 = 1.f;
        if (MODE == 1) { w0 = nb[s0]; w0 *= w0; }
        if (MODE == 2) { w0 = nb[s0]; }
        float4 v0 = *(const float4*)(h + (size_t)s0 * D + lane * 4);
        acc.x += w0 * v0.x; acc.y += w0 * v0.y;
        acc.z += w0 * v0.z; acc.w += w0 * v0.w;
    }
    float4 hv = *(const float4*)(h + (size_t)node * D + lane * 4);
    float4 r;
    if (MODE == 0) {
        r = make_float4(hv.x + acc.x, hv.y + acc.y, hv.z + acc.z, hv.w + acc.w);
    } else if (MODE == 1) {
        float a = nb[node];
        r = make_float4(a * (hv.x + acc.x), a * (hv.y + acc.y),
                        a * (hv.z + acc.z), a * (hv.w + acc.w));
    } else {
        float a = nb[node];
        r = make_float4(hv.x + a * acc.x, hv.y + a * acc.y,
                        hv.z + a * acc.z, hv.w + a * acc.w);
    }
    *(float4*)(agg + (size_t)node * D + lane * 4) = r;
}

// -------- pool + prototype argmax (pass 1): 256 threads, 4-way node parallel --------
__global__ void pool_argmax_k(const float* __restrict__ h, const int* __restrict__ gs,
                              const float* __restrict__ proto, const float* __restrict__ pnorm,
                              int* __restrict__ assign) {
    cudaGridDependencySynchronize();
    __shared__ float part[4][DD];
    int g = blockIdx.x, t = threadIdx.x;
    int grp = t >> 6, l = t & 63;
    int b = gs[g], e = gs[g + 1];
    float4 acc = make_float4(0.f, 0.f, 0.f, 0.f);
    for (int n = b + grp; n < e; n += 4) {
        float4 v = *(const float4*)(h + (size_t)n * DD + l * 4);
        acc.x += v.x; acc.y += v.y; acc.z += v.z; acc.w += v.w;
    }
    *(float4*)&part[grp][l * 4] = acc;
    __syncthreads();
    if (t < 64) {
        float4 a0 = *(float4*)&part[0][t * 4];
        float4 a1 = *(float4*)&part[1][t * 4];
        float4 a2 = *(float4*)&part[2][t * 4];
        float4 a3 = *(float4*)&part[3][t * 4];
        float4 r = make_float4(a0.x + a1.x + a2.x + a3.x, a0.y + a1.y + a2.y + a3.y,
                               a0.z + a1.z + a2.z + a3.z, a0.w + a1.w + a2.w + a3.w);
        *(float4*)&part[0][t * 4] = r;
    }
    __syncthreads();
    if (t < 32) {
        int lane = t;
        float ge[8];
        float ns = 0.f;
#pragma unroll
        for (int q = 0; q < 8; q++) { ge[q] = part[0][lane + q * 32]; ns += ge[q] * ge[q]; }
        ns = warp_sum(ns);
        float nrm = sqrtf(ns);
        if (nrm == 0.f) nrm = EPSV;
        float best = -1e30f;
        int bi = 0;
        for (int p = 0; p < PP; p++) {
            float d = 0.f;
#pragma unroll
            for (int q = 0; q < 8; q++) d += ge[q] * proto[(size_t)p * DD + lane + q * 32];
            d = warp_sum(d);
            float sim = d / (nrm * pnorm[p]);
            if (sim > best) { best = sim; bi = p; }
        }
        if (lane == 0) assign[g] = bi;
    }
}

// -------- gnorm from accumulated semb (d_out, 8B-aligned -> float2) --------
__global__ void gnorm_k(const float* __restrict__ semb, float* __restrict__ gnorm) {
    cudaGridDependencySynchronize();
    int g = blockIdx.x, t = threadIdx.x;   // 64 threads
    const float* row = semb + (size_t)g * DD + t * 4;
    float2 a = *(const float2*)(row);
    float2 b = *(const float2*)(row + 2);
    float sq = a.x * a.x + a.y * a.y + b.x * b.x + b.y * b.y;
    __shared__ float sh[2];
    int lane = t & 31, w = t >> 5;
#pragma unroll
    for (int o = 16; o > 0; o >>= 1) sq += __shfl_down_sync(0xffffffffu, sq, o);
    if (lane == 0) sh[w] = sq;
    __syncthreads();
    if (t == 0) {
        float s = sh[0] + sh[1];
        float n = sqrtf(s);
        if (n == 0.f) n = EPSV;
        gnorm[g] = n;
    }
}

// ======== TF32 tensor-core GEMM (128x128x16, 8 warps, m16n8k8) ========
__device__ __forceinline__ uint32_t f2tf(float f) {
    uint32_t r;
    asm("cvt.rna.tf32.f32 %0, %1;" : "=r"(r) : "f"(f));
    return r;
}
__device__ __forceinline__ void mma8(float* c, uint32_t a0, uint32_t a1, uint32_t a2,
                                     uint32_t a3, uint32_t b0, uint32_t b1) {
    asm volatile(
        "mma.sync.aligned.m16n8k8.row.col.f32.tf32.tf32.f32 "
        "{%0,%1,%2,%3}, {%4,%5,%6,%7}, {%8,%9}, {%0,%1,%2,%3};"
        : "+f"(c[0]), "+f"(c[1]), "+f"(c[2]), "+f"(c[3])
        : "r"(a0), "r"(a1), "r"(a2), "r"(a3), "r"(b0), "r"(b1));
}

#define TBM 128
#define TBN 128
#define TBK 16
#define ASTR 20
#define WSTR 136

// Epilogue sinks (any subset): C (float2 stores), C2 mirror, nprob dot, poolAcc
// (atomicAdd per element into poolAcc[batv[row]*Nout + col]).
__global__ __launch_bounds__(256, 2)
void gemm_tc_k(const float* __restrict__ A, const float* __restrict__ W,
               const float* __restrict__ bias, float* __restrict__ C,
               int M, int K, int Nout,
               const float* __restrict__ rowExtra, const int* __restrict__ batv,
               const int* __restrict__ assignv, float* __restrict__ C2,
               float* __restrict__ nprob, const float* __restrict__ Wm2v,
               float* __restrict__ poolAcc) {
    cudaGridDependencySynchronize();
    __shared__ uint32_t As[2][TBM * ASTR];
    __shared__ uint32_t Ws[2][TBK * WSTR];
    int bm = blockIdx.y * TBM, bn = blockIdx.x * TBN;
    int tid = threadIdx.x;
    int wid = tid >> 5, lane = tid & 31;
    int g = lane >> 2, tg = lane & 3;
    int wm = (wid & 1) * 64;
    int wn = (wid >> 1) * 32;

    int arow = tid >> 2;
    int acol = (tid & 3) * 4;
    int wrow = tid >> 5;
    int wcol = (tid & 31) * 4;
    int gr0 = bm + arow, gr1 = bm + arow + 64;

    const int kTiles = K / TBK;
    float4 a0g, a1g, w0g, w1g;

    {
        const float* Ab = A + acol;
        a0g = (gr0 < M) ? *(const float4*)(Ab + (size_t)gr0 * K) : make_float4(0,0,0,0);
        a1g = (gr1 < M) ? *(const float4*)(Ab + (size_t)gr1 * K) : make_float4(0,0,0,0);
        const float* Wb = W + (size_t)wrow * Nout + bn + wcol;
        w0g = *(const float4*)(Wb);
        w1g = *(const float4*)(Wb + (size_t)8 * Nout);
        uint4 p;
        p.x = f2tf(a0g.x); p.y = f2tf(a0g.y); p.z = f2tf(a0g.z); p.w = f2tf(a0g.w);
        *(uint4*)&As[0][arow * ASTR + acol] = p;
        p.x = f2tf(a1g.x); p.y = f2tf(a1g.y); p.z = f2tf(a1g.z); p.w = f2tf(a1g.w);
        *(uint4*)&As[0][(arow + 64) * ASTR + acol] = p;
        p.x = f2tf(w0g.x); p.y = f2tf(w0g.y); p.z = f2tf(w0g.z); p.w = f2tf(w0g.w);
        *(uint4*)&Ws[0][wrow * WSTR + wcol] = p;
        p.x = f2tf(w1g.x); p.y = f2tf(w1g.y); p.z = f2tf(w1g.z); p.w = f2tf(w1g.w);
        *(uint4*)&Ws[0][(wrow + 8) * WSTR + wcol] = p;
    }
    __syncthreads();

    float acc[4][4][4];
#pragma unroll
    for (int a = 0; a < 4; a++)
#pragma unroll
        for (int b = 0; b < 4; b++)
#pragma unroll
            for (int c = 0; c < 4; c++) acc[a][b][c] = 0.f;

    for (int t = 0; t < kTiles; t++) {
        int buf = t & 1;
        if (t + 1 < kTiles) {
            const float* Ab = A + (t + 1) * TBK + acol;
            a0g = (gr0 < M) ? *(const float4*)(Ab + (size_t)gr0 * K) : make_float4(0,0,0,0);
            a1g = (gr1 < M) ? *(const float4*)(Ab + (size_t)gr1 * K) : make_float4(0,0,0,0);
            const float* Wb = W + (size_t)((t + 1) * TBK + wrow) * Nout + bn + wcol;
            w0g = *(const float4*)(Wb);
            w1g = *(const float4*)(Wb + (size_t)8 * Nout);
        }
#pragma unroll
        for (int ks = 0; ks < TBK; ks += 8) {
            uint32_t af[4][4], bf[4][2];
#pragma unroll
            for (int mt = 0; mt < 4; mt++) {
                int r = wm + mt * 16 + g;
                af[mt][0] = As[buf][r * ASTR + ks + tg];
                af[mt][1] = As[buf][(r + 8) * ASTR + ks + tg];
                af[mt][2] = As[buf][r * ASTR + ks + tg + 4];
                af[mt][3] = As[buf][(r + 8) * ASTR + ks + tg + 4];
            }
#pragma unroll
            for (int nt = 0; nt < 4; nt++) {
                int c = wn + nt * 8 + g;
                bf[nt][0] = Ws[buf][(ks + tg) * WSTR + c];
                bf[nt][1] = Ws[buf][(ks + tg + 4) * WSTR + c];
            }
#pragma unroll
            for (int mt = 0; mt < 4; mt++)
#pragma unroll
                for (int nt = 0; nt < 4; nt++)
                    mma8(acc[mt][nt], af[mt][0], af[mt][1], af[mt][2], af[mt][3],
                         bf[nt][0], bf[nt][1]);
        }
        if (t + 1 < kTiles) {
            int nb_ = buf ^ 1;
            uint4 p;
            p.x = f2tf(a0g.x); p.y = f2tf(a0g.y); p.z = f2tf(a0g.z); p.w = f2tf(a0g.w);
            *(uint4*)&As[nb_][arow * ASTR + acol] = p;
            p.x = f2tf(a1g.x); p.y = f2tf(a1g.y); p.z = f2tf(a1g.z); p.w = f2tf(a1g.w);
            *(uint4*)&As[nb_][(arow + 64) * ASTR + acol] = p;
            p.x = f2tf(w0g.x); p.y = f2tf(w0g.y); p.z = f2tf(w0g.z); p.w = f2tf(w0g.w);
            *(uint4*)&Ws[nb_][wrow * WSTR + wcol] = p;
            p.x = f2tf(w1g.x); p.y = f2tf(w1g.y); p.z = f2tf(w1g.z); p.w = f2tf(w1g.w);
            *(uint4*)&Ws[nb_][(wrow + 8) * WSTR + wcol] = p;
        }
        __syncthreads();
    }

#pragma unroll
    for (int mt = 0; mt < 4; mt++) {
#pragma unroll
        for (int half = 0; half < 2; half++) {
            int row = bm + wm + mt * 16 + g + half * 8;
            bool rok = row < M;
            int rsafe = rok ? row : 0;
            const float* ex = rowExtra ? rowExtra + (size_t)assignv[batv[rsafe]] * Nout : nullptr;
            float* pl = nullptr;
            if (poolAcc && rok) pl = poolAcc + (size_t)batv[row] * Nout;
            float part = 0.f;
#pragma unroll
            for (int nt = 0; nt < 4; nt++) {
                int col = bn + wn + nt * 8 + tg * 2;
                float v0 = acc[mt][nt][half * 2 + 0] + bias[col];
                float v1 = acc[mt][nt][half * 2 + 1] + bias[col + 1];
                if (ex) { v0 += ex[col]; v1 += ex[col + 1]; }
                v0 = fmaxf(v0, 0.f); v1 = fmaxf(v1, 0.f);
                if (rok) {
                    if (C)  *(float2*)(C  + (size_t)row * Nout + col) = make_float2(v0, v1);
                    if (C2) *(float2*)(C2 + (size_t)row * Nout + col) = make_float2(v0, v1);
                    if (pl) { atomicAdd(pl + col, v0); atomicAdd(pl + col + 1, v1); }
                }
                if (nprob) part += v0 * Wm2v[col] + v1 * Wm2v[col + 1];
            }
            if (nprob) {
                part += __shfl_down_sync(0xffffffffu, part, 2);
                part += __shfl_down_sync(0xffffffffu, part, 1);
                if (tg == 0 && rok) atomicAdd(&nprob[row], part);
            }
        }
    }
}

// -------- sigmoid + node KL --------
__global__ void nprob_sig_k(const float* __restrict__ nprob, const float* __restrict__ bm2,
                            float* __restrict__ nb, float* __restrict__ nbout,
                            float* __restrict__ acc) {
    cudaGridDependencySynchronize();
    int i = blockIdx.x * blockDim.x + threadIdx.x;
    float term = 0.f;
    if (i < NN) {
        float s = 1.f / (1.f + expf(-(nprob[i] + bm2[0])));
        nb[i] = s; nbout[i] = s;
        term = s * logf(s / 0.5f + EPSV)
             + (1.f - s) * logf((1.f - s) / (1.f - 0.5f + EPSV) + EPSV);
    }
    block_atomic_add(term, acc);
}

// -------- edge bern + edge KL --------
__global__ void edgebern_k(const float* __restrict__ nb, const int* __restrict__ src,
                           const int* __restrict__ dst, float* __restrict__ out,
                           float* __restrict__ acc) {
    cudaGridDependencySynchronize();
    int i = blockIdx.x * blockDim.x + threadIdx.x;
    float term = 0.f;
    if (i < EE) {
        float v = nb[src[i]] * nb[dst[i]];
        out[i] = v;
        term = v * logf(v / 0.25f + EPSV)
             + (1.f - v) * logf((1.f - v) / (1.f - 0.25f + EPSV) + EPSV);
    }
    block_atomic_add(term, acc + 1);
}

// -------- fused similarity/NCE + data_sim + finalize --------
__global__ void simdata_k(const float* __restrict__ semb, const float* __restrict__ gnorm,
                          const float* __restrict__ proto, const float* __restrict__ pnorm,
                          float* __restrict__ simout, float* __restrict__ dsout,
                          float* __restrict__ acc, int* __restrict__ done,
                          float* __restrict__ out) {
    cudaGridDependencySynchronize();
    __shared__ float ri[DD];
    int i = blockIdx.x, tid = threadIdx.x, lane = tid & 31, w = tid >> 5;
    ri[tid] = semb[(size_t)i * DD + tid];
    __syncthreads();
    float ni = gnorm[i];
    if (tid < 32) {
        float ge[8];
#pragma unroll
        for (int q = 0; q < 8; q++) ge[q] = ri[lane + q * 32];
        float best = -1e30f, pos = 0.f, sum = 0.f;
        for (int p = 0; p < PP; p++) {
            float d = 0.f;
#pragma unroll
            for (int q = 0; q < 8; q++) d += ge[q] * proto[(size_t)p * DD + lane + q * 32];
            d = warp_sum(d);
            float sim = d / (ni * pnorm[p]);
            if (lane == 0) simout[(size_t)i * PP + p] = sim;
            float se = expf(sim / TEMPV);
            sum += se;
            if (sim > best) { best = sim; pos = se; }
        }
        if (lane == 0) atomicAdd(&acc[2], -logf(pos / (sum - pos)));
    }
    for (int j = w; j < GG; j += 8) {
        float d = 0.f;
#pragma unroll
        for (int q = 0; q < 8; q++) {
            int c = lane + q * 32;
            d += ri[c] * semb[(size_t)j * DD + c];
        }
        d = warp_sum(d);
        if (lane == 0) dsout[(size_t)i * GG + j] = d / (ni * gnorm[j]);
    }
    __syncthreads();
    if (tid == 0) {
        __threadfence();
        int t = atomicAdd(done, 1);
        if (t == GG - 1) {
            __threadfence();
            out[O_KL]  = acc[0] / (float)NN + acc[1] / (float)EE;
            out[O_NCE] = acc[2] / (float)GG;
        }
    }
}

// -------- PDL launch helper --------
template <typename... Args>
static inline void launch_pdl(void (*kern)(Args...), dim3 grid, dim3 block, Args... args) {
    cudaLaunchConfig_t cfg = {};
    cfg.gridDim = grid;
    cfg.blockDim = block;
    cfg.dynamicSmemBytes = 0;
    cudaLaunchAttribute attr[1];
    attr[0].id = cudaLaunchAttributeProgrammaticStreamSerialization;
    attr[0].val.programmaticStreamSerializationAllowed = 1;
    cfg.attrs = attr;
    cfg.numAttrs = 1;
    cudaLaunchKernelEx(&cfg, kern, args...);
}

// =====================================================================
extern "C" void kernel_launch(void* const* d_in, const int* in_sizes, int n_in,
                              void* d_out, int out_size) {
    const float* x    = (const float*)d_in[0];
    const int*   ei   = (const int*)d_in[1];
    const int*   bat  = (const int*)d_in[2];
    const float* W1   = (const float*)d_in[3];
    const float* b1   = (const float*)d_in[4];
    const float* W2   = (const float*)d_in[5];
    const float* b2   = (const float*)d_in[6];
    const float* Wm1  = (const float*)d_in[7];
    const float* bm1  = (const float*)d_in[8];
    const float* Wm2  = (const float*)d_in[9];
    const float* bm2  = (const float*)d_in[10];
    const float* prot = (const float*)d_in[11];
    float* out = (float*)d_out;

    const int* src = ei;
    const int* dst = ei + EE;

    float *agg, *h1, *h2, *pnorm, *gnorm, *contrib, *nb, *nprob, *acc;
    int *assign, *cnt, *ptr, *cursor, *csrc, *gstart, *bsum, *done;
    cudaGetSymbolAddress((void**)&agg, g_agg);
    cudaGetSymbolAddress((void**)&h1, g_h1);
    cudaGetSymbolAddress((void**)&h2, g_h2);
    cudaGetSymbolAddress((void**)&pnorm, g_pnorm);
    cudaGetSymbolAddress((void**)&gnorm, g_gnorm);
    cudaGetSymbolAddress((void**)&contrib, g_contrib);
    cudaGetSymbolAddress((void**)&nb, g_nb);
    cudaGetSymbolAddress((void**)&nprob, g_nprob);
    cudaGetSymbolAddress((void**)&acc, g_acc);
    cudaGetSymbolAddress((void**)&assign, g_assign);
    cudaGetSymbolAddress((void**)&cnt, g_cnt);
    cudaGetSymbolAddress((void**)&ptr, g_ptr);
    cudaGetSymbolAddress((void**)&cursor, g_cursor);
    cudaGetSymbolAddress((void**)&csrc, g_csrc);
    cudaGetSymbolAddress((void**)&gstart, g_gstart);
    cudaGetSymbolAddress((void**)&bsum, g_bsum);
    cudaGetSymbolAddress((void**)&done, g_done);

    auto blks = [](long n, int t) { return (int)((n + t - 1) / t); };

    // ---- init + CSR build ----
    launch_pdl(init_k, dim3(SCAN_B + 2 + SE_B), dim3(256),
               cnt, cursor, nprob, acc, done, bat, gstart, out + O_SE);
    launch_pdl(hist_k, dim3(blks(EE, 256)), dim3(256), dst, cnt);
    launch_pdl(scan1_k, dim3(SCAN_B), dim3(256), (const int*)cnt, ptr, bsum);
    launch_pdl(scan2_k, dim3(SCAN_B), dim3(256), ptr, (const int*)bsum);
    launch_pdl(fill_k, dim3(blks(EE, 256)), dim3(256),
               src, dst, (const int*)ptr, cursor, csrc);
    launch_pdl(protprep_k, dim3(PP), dim3(DD), prot, Wm1, contrib, pnorm);

    dim3 gg(DD / TBN, (NN + TBM - 1) / TBM);

    // ---- pass 1 ----
    launch_pdl(gather_k<INF, 0>, dim3(blks(NN, 8)), dim3(256),
               x, (const int*)ptr, (const int*)csrc, (const float*)nullptr, agg);
    launch_pdl(gemm_tc_k, gg, dim3(256),
               (const float*)agg, W1, b1, h1, NN, INF, DD,
               (const float*)nullptr, (const int*)nullptr, (const int*)nullptr,
               (float*)nullptr, (float*)nullptr, (const float*)nullptr, (float*)nullptr);
    launch_pdl(gather_k<DD, 0>, dim3(blks(NN, 4)), dim3(256),
               (const float*)h1, (const int*)ptr, (const int*)csrc,
               (const float*)nullptr, agg);
    launch_pdl(gemm_tc_k, gg, dim3(256),
               (const float*)agg, W2, b2, h2, NN, DD, DD,
               (const float*)nullptr, (const int*)nullptr, (const int*)nullptr,
               out + O_NE, (float*)nullptr, (const float*)nullptr, (float*)nullptr);
    launch_pdl(pool_argmax_k, dim3(GG), dim3(256),
               (const float*)h2, (const int*)gstart, prot, (const float*)pnorm, assign);

    // ---- MLP (nodeprob dot fused into GEMM epilogue; hid not written) ----
    launch_pdl(gemm_tc_k, gg, dim3(256),
               (const float*)h2, Wm1, bm1, (float*)nullptr, NN, DD, DD,
               (const float*)contrib, bat, (const int*)assign,
               (float*)nullptr, nprob, Wm2, (float*)nullptr);
    launch_pdl(nprob_sig_k, dim3(SCAN_B), dim3(256),
               (const float*)nprob, bm2, nb, out + O_NB, acc);
    launch_pdl(edgebern_k, dim3(blks(EE, 256)), dim3(256),
               (const float*)nb, src, dst, out + O_EB, acc);

    // ---- pass 2 ----
    launch_pdl(gather_k<INF, 1>, dim3(blks(NN, 8)), dim3(256),
               x, (const int*)ptr, (const int*)csrc, (const float*)nb, agg);
    launch_pdl(gemm_tc_k, gg, dim3(256),
               (const float*)agg, W1, b1, h1, NN, INF, DD,
               (const float*)nullptr, (const int*)nullptr, (const int*)nullptr,
               (float*)nullptr, (float*)nullptr, (const float*)nullptr, (float*)nullptr);
    launch_pdl(gather_k<DD, 2>, dim3(blks(NN, 4)), dim3(256),
               (const float*)h1, (const int*)ptr, (const int*)csrc,
               (const float*)nb, agg);
    // conv2 GEMM pools directly into out[O_SE] via atomics (no hid buffer)
    launch_pdl(gemm_tc_k, gg, dim3(256),
               (const float*)agg, W2, b2, (float*)nullptr, NN, DD, DD,
               (const float*)nullptr, bat, (const int*)nullptr,
               (float*)nullptr, (float*)nullptr, (const float*)nullptr, out + O_SE);
    launch_pdl(gnorm_k, dim3(GG), dim3(64), (const float*)(out + O_SE), gnorm);

    // ---- similarity / NCE / data_sim / finalize ----
    launch_pdl(simdata_k, dim3(GG), dim3(DD),
               (const float*)(out + O_SE), (const float*)gnorm, prot,
               (const float*)pnorm, out + O_SIM, out + O_DS, acc, done, out);
}

// round 17
// speedup vs baseline: 1.0688x; 1.0651x over previous
#include <cuda_runtime.h>
#include <math.h>
#include <stdint.h>

static constexpr int NN  = 20000;
static constexpr int EE  = 320000;
static constexpr int GG  = 256;
static constexpr int INF = 128;
static constexpr int DD  = 256;
static constexpr int PP  = 16;
#define EPSV 1e-7f
#define TEMPV 0.2f

static constexpr size_t O_KL  = 0;
static constexpr size_t O_NCE = 1;
static constexpr size_t O_SIM = 2;
static constexpr size_t O_NB  = O_SIM + (size_t)GG*PP;
static constexpr size_t O_EB  = O_NB  + NN;
static constexpr size_t O_DS  = O_EB  + EE;
static constexpr size_t O_SE  = O_DS  + (size_t)GG*GG;
static constexpr size_t O_NE  = O_SE  + (size_t)GG*DD;
// d_out at O_SE/O_NE is only 8-byte aligned: NEVER 16B access into d_out.

static constexpr int SCAN_B = (NN + 255) / 256;   // 79

// -------- device scratch --------
__device__ __align__(16) float g_agg[(size_t)NN*DD];
__device__ __align__(16) float g_h1 [(size_t)NN*DD];
__device__ __align__(16) float g_h2 [(size_t)NN*DD];
__device__ __align__(16) float g_hid[(size_t)NN*DD];
__device__ float g_pnorm[PP];
__device__ float g_gnorm[GG];
__device__ float g_contrib[PP*DD];
__device__ float g_nb[NN];
__device__ float g_nprob[NN];
__device__ int   g_assign[GG];
__device__ float g_acc[4];
__device__ int   g_done;
__device__ int g_cnt[NN];
__device__ int g_ptr[NN + 1];
__device__ int g_cursor[NN];
__device__ int g_csrc[EE];
__device__ int g_gstart[GG + 1];
__device__ int g_bsum[SCAN_B];

__device__ __forceinline__ float warp_sum(float v) {
#pragma unroll
    for (int o = 16; o > 0; o >>= 1) v += __shfl_down_sync(0xffffffffu, v, o);
    return __shfl_sync(0xffffffffu, v, 0);
}

__device__ __forceinline__ void block_atomic_add(float v, float* slot) {
    __shared__ float sh[8];
#pragma unroll
    for (int o = 16; o > 0; o >>= 1) v += __shfl_down_sync(0xffffffffu, v, o);
    if ((threadIdx.x & 31) == 0) sh[threadIdx.x >> 5] = v;
    __syncthreads();
    if (threadIdx.x == 0) {
        float t = 0.f;
        int nw = blockDim.x >> 5;
        for (int q = 0; q < nw; q++) t += sh[q];
        atomicAdd(slot, t);
    }
}

// -------- init: zero scratch + gstart --------
__global__ void init_k(int* __restrict__ cnt, int* __restrict__ cursor,
                       float* __restrict__ nprob, float* __restrict__ acc,
                       int* __restrict__ done,
                       const int* __restrict__ batch, int* __restrict__ gs) {
    cudaGridDependencySynchronize();
    int b = blockIdx.x, t = threadIdx.x;
    if (b < SCAN_B) {
        int i = b * 256 + t;
        if (i < NN) { cnt[i] = 0; cursor[i] = 0; nprob[i] = 0.f; }
        if (b == 0) {
            if (t < 4) acc[t] = 0.f;
            if (t == 4) *done = 0;
        }
    } else {
        int g = (b - SCAN_B) * 256 + t;
        if (g > GG) return;
        if (g == GG) { gs[GG] = NN; return; }
        int lo = 0, hi = NN;
        while (lo < hi) { int mid = (lo + hi) >> 1; if (batch[mid] < g) lo = mid + 1; else hi = mid; }
        gs[g] = lo;
    }
}

// -------- CSR build --------
__global__ void hist_k(const int* __restrict__ dst, int* __restrict__ cnt) {
    cudaGridDependencySynchronize();
    int e = blockIdx.x * blockDim.x + threadIdx.x;
    if (e < EE) atomicAdd(&cnt[dst[e]], 1);
}

__global__ void scan1_k(const int* __restrict__ cnt, int* __restrict__ ptr,
                        int* __restrict__ bsum) {
    cudaGridDependencySynchronize();
    int i = blockIdx.x * 256 + threadIdx.x;
    int lane = threadIdx.x & 31, w = threadIdx.x >> 5;
    int v = (i < NN) ? cnt[i] : 0;
    int s = v;
#pragma unroll
    for (int o = 1; o < 32; o <<= 1) {
        int t = __shfl_up_sync(0xffffffffu, s, o);
        if (lane >= o) s += t;
    }
    __shared__ int ws[8];
    if (lane == 31) ws[w] = s;
    __syncthreads();
    if (threadIdx.x < 8) {
        int t = ws[threadIdx.x];
#pragma unroll
        for (int o = 1; o < 8; o <<= 1) {
            int u = __shfl_up_sync(0xffu, t, o);
            if ((int)threadIdx.x >= o) t += u;
        }
        ws[threadIdx.x] = t;
    }
    __syncthreads();
    int excl = s - v + (w ? ws[w - 1] : 0);
    if (i < NN) ptr[i] = excl;
    if (threadIdx.x == 255) bsum[blockIdx.x] = excl + v;
}

__global__ void scan2_k(int* __restrict__ ptr, const int* __restrict__ bsum) {
    cudaGridDependencySynchronize();
    int b = blockIdx.x;
    int partial = 0;
    for (int j = threadIdx.x; j < b; j += 256) partial += bsum[j];
    __shared__ int sh[8];
    int lane = threadIdx.x & 31, w = threadIdx.x >> 5;
#pragma unroll
    for (int o = 16; o > 0; o >>= 1) partial += __shfl_down_sync(0xffffffffu, partial, o);
    if (lane == 0) sh[w] = partial;
    __syncthreads();
    __shared__ int off;
    if (threadIdx.x == 0) {
        int t = 0;
#pragma unroll
        for (int q = 0; q < 8; q++) t += sh[q];
        off = t;
    }
    __syncthreads();
    int i = b * 256 + threadIdx.x;
    if (i < NN) ptr[i] += off;
    if (b == gridDim.x - 1 && threadIdx.x == 0) ptr[NN] = off + bsum[b];
}

__global__ void fill_k(const int* __restrict__ src, const int* __restrict__ dst,
                       const int* __restrict__ ptr, int* __restrict__ cursor,
                       int* __restrict__ csrc) {
    cudaGridDependencySynchronize();
    int e = blockIdx.x * blockDim.x + threadIdx.x;
    if (e >= EE) return;
    int d = dst[e];
    int s = atomicAdd(&cursor[d], 1);
    csrc[ptr[d] + s] = src[e];
}

// -------- prototype prep --------
__global__ void protprep_k(const float* __restrict__ proto, const float* __restrict__ Wm1,
                           float* __restrict__ contrib, float* __restrict__ pnorm) {
    cudaGridDependencySynchronize();
    __shared__ float pr[DD];
    int p = blockIdx.x, tid = threadIdx.x;
    float e = proto[(size_t)p * DD + tid];
    pr[tid] = e;
    __syncthreads();
    float a = 0.f;
    for (int k = 0; k < DD; k++) a += pr[k] * Wm1[(size_t)(DD + k) * DD + tid];
    contrib[(size_t)p * DD + tid] = a;
    float sq = e * e;
    __shared__ float sh[8];
    int lane = tid & 31, w = tid >> 5;
#pragma unroll
    for (int o = 16; o > 0; o >>= 1) sq += __shfl_down_sync(0xffffffffu, sq, o);
    if (lane == 0) sh[w] = sq;
    __syncthreads();
    if (tid == 0) {
        float t = 0.f;
#pragma unroll
        for (int q = 0; q < 8; q++) t += sh[q];
        float n = sqrtf(t);
        if (n == 0.f) n = EPSV;
        pnorm[p] = n;
    }
}

// -------- gather (fp32, 2-way edge unroll — proven config) --------
// MODE 0: agg = h[n] + sum h[s]
// MODE 1: agg = nb[n]*(h[n] + sum nb[s]^2 h[s])
// MODE 2: agg = h[n] + nb[n]*sum nb[s] h[s]
template <int D, int MODE>
__global__ void gather_k(const float* __restrict__ h, const int* __restrict__ ptr,
                         const int* __restrict__ csrc, const float* __restrict__ nb,
                         float* __restrict__ agg) {
    cudaGridDependencySynchronize();
    constexpr int TPN = D / 4;
    constexpr int NPB = 256 / TPN;
    int node = blockIdx.x * NPB + threadIdx.x / TPN;
    int lane = threadIdx.x % TPN;
    if (node >= NN) return;
    int b = ptr[node], e = ptr[node + 1];
    float4 acc = make_float4(0.f, 0.f, 0.f, 0.f);
    int i = b;
    for (; i + 2 <= e; i += 2) {
        int s0 = csrc[i], s1 = csrc[i + 1];
        float w0 = 1.f, w1 = 1.f;
        if (MODE == 1) { w0 = nb[s0]; w0 *= w0; w1 = nb[s1]; w1 *= w1; }
        if (MODE == 2) { w0 = nb[s0]; w1 = nb[s1]; }
        float4 v0 = *(const float4*)(h + (size_t)s0 * D + lane * 4);
        float4 v1 = *(const float4*)(h + (size_t)s1 * D + lane * 4);
        acc.x += w0 * v0.x + w1 * v1.x;
        acc.y += w0 * v0.y + w1 * v1.y;
        acc.z += w0 * v0.z + w1 * v1.z;
        acc.w += w0 * v0.w + w1 * v1.w;
    }
    if (i < e) {
        int s0 = csrc[i];
        float w0 = 1.f;
        if (MODE == 1) { w0 = nb[s0]; w0 *= w0; }
        if (MODE == 2) { w0 = nb[s0]; }
        float4 v0 = *(const float4*)(h + (size_t)s0 * D + lane * 4);
        acc.x += w0 * v0.x; acc.y += w0 * v0.y;
        acc.z += w0 * v0.z; acc.w += w0 * v0.w;
    }
    float4 hv = *(const float4*)(h + (size_t)node * D + lane * 4);
    float4 r;
    if (MODE == 0) {
        r = make_float4(hv.x + acc.x, hv.y + acc.y, hv.z + acc.z, hv.w + acc.w);
    } else if (MODE == 1) {
        float a = nb[node];
        r = make_float4(a * (hv.x + acc.x), a * (hv.y + acc.y),
                        a * (hv.z + acc.z), a * (hv.w + acc.w));
    } else {
        float a = nb[node];
        r = make_float4(hv.x + a * acc.x, hv.y + a * acc.y,
                        hv.z + a * acc.z, hv.w + a * acc.w);
    }
    *(float4*)(agg + (size_t)node * D + lane * 4) = r;
}

// -------- pool + prototype argmax (pass 1): 256 threads, 4-way node parallel --------
__global__ void pool_argmax_k(const float* __restrict__ h, const int* __restrict__ gs,
                              const float* __restrict__ proto, const float* __restrict__ pnorm,
                              int* __restrict__ assign) {
    cudaGridDependencySynchronize();
    __shared__ float part[4][DD];
    int g = blockIdx.x, t = threadIdx.x;
    int grp = t >> 6, l = t & 63;
    int b = gs[g], e = gs[g + 1];
    float4 acc = make_float4(0.f, 0.f, 0.f, 0.f);
    for (int n = b + grp; n < e; n += 4) {
        float4 v = *(const float4*)(h + (size_t)n * DD + l * 4);
        acc.x += v.x; acc.y += v.y; acc.z += v.z; acc.w += v.w;
    }
    *(float4*)&part[grp][l * 4] = acc;
    __syncthreads();
    if (t < 64) {
        float4 a0 = *(float4*)&part[0][t * 4];
        float4 a1 = *(float4*)&part[1][t * 4];
        float4 a2 = *(float4*)&part[2][t * 4];
        float4 a3 = *(float4*)&part[3][t * 4];
        float4 r = make_float4(a0.x + a1.x + a2.x + a3.x, a0.y + a1.y + a2.y + a3.y,
                               a0.z + a1.z + a2.z + a3.z, a0.w + a1.w + a2.w + a3.w);
        *(float4*)&part[0][t * 4] = r;   // own columns only: no race
    }
    __syncthreads();
    if (t < 32) {
        int lane = t;
        float ge[8];
        float ns = 0.f;
#pragma unroll
        for (int q = 0; q < 8; q++) { ge[q] = part[0][lane + q * 32]; ns += ge[q] * ge[q]; }
        ns = warp_sum(ns);
        float nrm = sqrtf(ns);
        if (nrm == 0.f) nrm = EPSV;
        float best = -1e30f;
        int bi = 0;
        for (int p = 0; p < PP; p++) {
            float d = 0.f;
#pragma unroll
            for (int q = 0; q < 8; q++) d += ge[q] * proto[(size_t)p * DD + lane + q * 32];
            d = warp_sum(d);
            float sim = d / (nrm * pnorm[p]);
            if (sim > best) { best = sim; bi = p; }
        }
        if (lane == 0) assign[g] = bi;
    }
}

// -------- pool + row norm (pass 2): 256 threads, 4-way node parallel --------
__global__ void pool_norm_k(const float* __restrict__ h, const int* __restrict__ gs,
                            float* __restrict__ gout, float* __restrict__ gnorm) {
    cudaGridDependencySynchronize();
    __shared__ float part[4][DD];
    int g = blockIdx.x, t = threadIdx.x;
    int grp = t >> 6, l = t & 63;
    int b = gs[g], e = gs[g + 1];
    float4 acc = make_float4(0.f, 0.f, 0.f, 0.f);
    for (int n = b + grp; n < e; n += 4) {
        float4 v = *(const float4*)(h + (size_t)n * DD + l * 4);
        acc.x += v.x; acc.y += v.y; acc.z += v.z; acc.w += v.w;
    }
    *(float4*)&part[grp][l * 4] = acc;
    __syncthreads();
    if (t < 64) {
        float4 a0 = *(float4*)&part[0][t * 4];
        float4 a1 = *(float4*)&part[1][t * 4];
        float4 a2 = *(float4*)&part[2][t * 4];
        float4 a3 = *(float4*)&part[3][t * 4];
        float4 r = make_float4(a0.x + a1.x + a2.x + a3.x, a0.y + a1.y + a2.y + a3.y,
                               a0.z + a1.z + a2.z + a3.z, a0.w + a1.w + a2.w + a3.w);
        float* o = gout + (size_t)g * DD + t * 4;
        *(float2*)(o)     = make_float2(r.x, r.y);   // d_out 8B-aligned: float2 only
        *(float2*)(o + 2) = make_float2(r.z, r.w);
        *(float4*)&part[0][t * 4] = r;
    }
    __syncthreads();
    if (t < 32) {
        float sq = 0.f;
#pragma unroll
        for (int q = 0; q < 8; q++) {
            float v = part[0][t + q * 32];
            sq += v * v;
        }
        sq = warp_sum(sq);
        if (t == 0) {
            float n = sqrtf(sq);
            if (n == 0.f) n = EPSV;
            gnorm[g] = n;
        }
    }
}

// ======== TF32 tensor-core GEMM (128x128x16, 8 warps, m16n8k8) ========
__device__ __forceinline__ uint32_t f2tf(float f) {
    uint32_t r;
    asm("cvt.rna.tf32.f32 %0, %1;" : "=r"(r) : "f"(f));
    return r;
}
__device__ __forceinline__ void mma8(float* c, uint32_t a0, uint32_t a1, uint32_t a2,
                                     uint32_t a3, uint32_t b0, uint32_t b1) {
    asm volatile(
        "mma.sync.aligned.m16n8k8.row.col.f32.tf32.tf32.f32 "
        "{%0,%1,%2,%3}, {%4,%5,%6,%7}, {%8,%9}, {%0,%1,%2,%3};"
        : "+f"(c[0]), "+f"(c[1]), "+f"(c[2]), "+f"(c[3])
        : "r"(a0), "r"(a1), "r"(a2), "r"(a3), "r"(b0), "r"(b1));
}

#define TBM 128
#define TBN 128
#define TBK 16
#define ASTR 20
#define WSTR 136

__global__ __launch_bounds__(256, 2)
void gemm_tc_k(const float* __restrict__ A, const float* __restrict__ W,
               const float* __restrict__ bias, float* __restrict__ C,
               int M, int K, int Nout,
               const float* __restrict__ rowExtra, const int* __restrict__ batv,
               const int* __restrict__ assignv, float* __restrict__ C2,
               float* __restrict__ nprob, const float* __restrict__ Wm2v) {
    cudaGridDependencySynchronize();
    __shared__ uint32_t As[2][TBM * ASTR];
    __shared__ uint32_t Ws[2][TBK * WSTR];
    int bm = blockIdx.y * TBM, bn = blockIdx.x * TBN;
    int tid = threadIdx.x;
    int wid = tid >> 5, lane = tid & 31;
    int g = lane >> 2, tg = lane & 3;
    int wm = (wid & 1) * 64;
    int wn = (wid >> 1) * 32;

    int arow = tid >> 2;
    int acol = (tid & 3) * 4;
    int wrow = tid >> 5;
    int wcol = (tid & 31) * 4;
    int gr0 = bm + arow, gr1 = bm + arow + 64;

    const int kTiles = K / TBK;
    float4 a0g, a1g, w0g, w1g;

    {
        const float* Ab = A + acol;
        a0g = (gr0 < M) ? *(const float4*)(Ab + (size_t)gr0 * K) : make_float4(0,0,0,0);
        a1g = (gr1 < M) ? *(const float4*)(Ab + (size_t)gr1 * K) : make_float4(0,0,0,0);
        const float* Wb = W + (size_t)wrow * Nout + bn + wcol;
        w0g = *(const float4*)(Wb);
        w1g = *(const float4*)(Wb + (size_t)8 * Nout);
        uint4 p;
        p.x = f2tf(a0g.x); p.y = f2tf(a0g.y); p.z = f2tf(a0g.z); p.w = f2tf(a0g.w);
        *(uint4*)&As[0][arow * ASTR + acol] = p;
        p.x = f2tf(a1g.x); p.y = f2tf(a1g.y); p.z = f2tf(a1g.z); p.w = f2tf(a1g.w);
        *(uint4*)&As[0][(arow + 64) * ASTR + acol] = p;
        p.x = f2tf(w0g.x); p.y = f2tf(w0g.y); p.z = f2tf(w0g.z); p.w = f2tf(w0g.w);
        *(uint4*)&Ws[0][wrow * WSTR + wcol] = p;
        p.x = f2tf(w1g.x); p.y = f2tf(w1g.y); p.z = f2tf(w1g.z); p.w = f2tf(w1g.w);
        *(uint4*)&Ws[0][(wrow + 8) * WSTR + wcol] = p;
    }
    __syncthreads();

    float acc[4][4][4];
#pragma unroll
    for (int a = 0; a < 4; a++)
#pragma unroll
        for (int b = 0; b < 4; b++)
#pragma unroll
            for (int c = 0; c < 4; c++) acc[a][b][c] = 0.f;

    for (int t = 0; t < kTiles; t++) {
        int buf = t & 1;
        if (t + 1 < kTiles) {
            const float* Ab = A + (t + 1) * TBK + acol;
            a0g = (gr0 < M) ? *(const float4*)(Ab + (size_t)gr0 * K) : make_float4(0,0,0,0);
            a1g = (gr1 < M) ? *(const float4*)(Ab + (size_t)gr1 * K) : make_float4(0,0,0,0);
            const float* Wb = W + (size_t)((t + 1) * TBK + wrow) * Nout + bn + wcol;
            w0g = *(const float4*)(Wb);
            w1g = *(const float4*)(Wb + (size_t)8 * Nout);
        }
#pragma unroll
        for (int ks = 0; ks < TBK; ks += 8) {
            uint32_t af[4][4], bf[4][2];
#pragma unroll
            for (int mt = 0; mt < 4; mt++) {
                int r = wm + mt * 16 + g;
                af[mt][0] = As[buf][r * ASTR + ks + tg];
                af[mt][1] = As[buf][(r + 8) * ASTR + ks + tg];
                af[mt][2] = As[buf][r * ASTR + ks + tg + 4];
                af[mt][3] = As[buf][(r + 8) * ASTR + ks + tg + 4];
            }
#pragma unroll
            for (int nt = 0; nt < 4; nt++) {
                int c = wn + nt * 8 + g;
                bf[nt][0] = Ws[buf][(ks + tg) * WSTR + c];
                bf[nt][1] = Ws[buf][(ks + tg + 4) * WSTR + c];
            }
#pragma unroll
            for (int mt = 0; mt < 4; mt++)
#pragma unroll
                for (int nt = 0; nt < 4; nt++)
                    mma8(acc[mt][nt], af[mt][0], af[mt][1], af[mt][2], af[mt][3],
                         bf[nt][0], bf[nt][1]);
        }
        if (t + 1 < kTiles) {
            int nb_ = buf ^ 1;
            uint4 p;
            p.x = f2tf(a0g.x); p.y = f2tf(a0g.y); p.z = f2tf(a0g.z); p.w = f2tf(a0g.w);
            *(uint4*)&As[nb_][arow * ASTR + acol] = p;
            p.x = f2tf(a1g.x); p.y = f2tf(a1g.y); p.z = f2tf(a1g.z); p.w = f2tf(a1g.w);
            *(uint4*)&As[nb_][(arow + 64) * ASTR + acol] = p;
            p.x = f2tf(w0g.x); p.y = f2tf(w0g.y); p.z = f2tf(w0g.z); p.w = f2tf(w0g.w);
            *(uint4*)&Ws[nb_][wrow * WSTR + wcol] = p;
            p.x = f2tf(w1g.x); p.y = f2tf(w1g.y); p.z = f2tf(w1g.z); p.w = f2tf(w1g.w);
            *(uint4*)&Ws[nb_][(wrow + 8) * WSTR + wcol] = p;
        }
        __syncthreads();
    }

#pragma unroll
    for (int mt = 0; mt < 4; mt++) {
#pragma unroll
        for (int half = 0; half < 2; half++) {
            int row = bm + wm + mt * 16 + g + half * 8;
            bool rok = row < M;
            int rsafe = rok ? row : 0;
            const float* ex = rowExtra ? rowExtra + (size_t)assignv[batv[rsafe]] * Nout : nullptr;
            float part = 0.f;
#pragma unroll
            for (int nt = 0; nt < 4; nt++) {
                int col = bn + wn + nt * 8 + tg * 2;
                float v0 = acc[mt][nt][half * 2 + 0] + bias[col];
                float v1 = acc[mt][nt][half * 2 + 1] + bias[col + 1];
                if (ex) { v0 += ex[col]; v1 += ex[col + 1]; }
                v0 = fmaxf(v0, 0.f); v1 = fmaxf(v1, 0.f);
                if (rok) {
                    if (C)  *(float2*)(C  + (size_t)row * Nout + col) = make_float2(v0, v1);
                    if (C2) *(float2*)(C2 + (size_t)row * Nout + col) = make_float2(v0, v1);
                }
                if (nprob) part += v0 * Wm2v[col] + v1 * Wm2v[col + 1];
            }
            if (nprob) {
                part += __shfl_down_sync(0xffffffffu, part, 2);
                part += __shfl_down_sync(0xffffffffu, part, 1);
                if (tg == 0 && rok) atomicAdd(&nprob[row], part);
            }
        }
    }
}

// -------- sigmoid + node KL --------
__global__ void nprob_sig_k(const float* __restrict__ nprob, const float* __restrict__ bm2,
                            float* __restrict__ nb, float* __restrict__ nbout,
                            float* __restrict__ acc) {
    cudaGridDependencySynchronize();
    int i = blockIdx.x * blockDim.x + threadIdx.x;
    float term = 0.f;
    if (i < NN) {
        float s = 1.f / (1.f + expf(-(nprob[i] + bm2[0])));
        nb[i] = s; nbout[i] = s;
        term = s * logf(s / 0.5f + EPSV)
             + (1.f - s) * logf((1.f - s) / (1.f - 0.5f + EPSV) + EPSV);
    }
    block_atomic_add(term, acc);
}

// -------- edge bern + edge KL --------
__global__ void edgebern_k(const float* __restrict__ nb, const int* __restrict__ src,
                           const int* __restrict__ dst, float* __restrict__ out,
                           float* __restrict__ acc) {
    cudaGridDependencySynchronize();
    int i = blockIdx.x * blockDim.x + threadIdx.x;
    float term = 0.f;
    if (i < EE) {
        float v = nb[src[i]] * nb[dst[i]];
        out[i] = v;
        term = v * logf(v / 0.25f + EPSV)
             + (1.f - v) * logf((1.f - v) / (1.f - 0.25f + EPSV) + EPSV);
    }
    block_atomic_add(term, acc + 1);
}

// -------- fused similarity/NCE + data_sim + finalize --------
__global__ void simdata_k(const float* __restrict__ semb, const float* __restrict__ gnorm,
                          const float* __restrict__ proto, const float* __restrict__ pnorm,
                          float* __restrict__ simout, float* __restrict__ dsout,
                          float* __restrict__ acc, int* __restrict__ done,
                          float* __restrict__ out) {
    cudaGridDependencySynchronize();
    __shared__ float ri[DD];
    int i = blockIdx.x, tid = threadIdx.x, lane = tid & 31, w = tid >> 5;
    ri[tid] = semb[(size_t)i * DD + tid];
    __syncthreads();
    float ni = gnorm[i];
    if (tid < 32) {
        float ge[8];
#pragma unroll
        for (int q = 0; q < 8; q++) ge[q] = ri[lane + q * 32];
        float best = -1e30f, pos = 0.f, sum = 0.f;
        for (int p = 0; p < PP; p++) {
            float d = 0.f;
#pragma unroll
            for (int q = 0; q < 8; q++) d += ge[q] * proto[(size_t)p * DD + lane + q * 32];
            d = warp_sum(d);
            float sim = d / (ni * pnorm[p]);
            if (lane == 0) simout[(size_t)i * PP + p] = sim;
            float se = expf(sim / TEMPV);
            sum += se;
            if (sim > best) { best = sim; pos = se; }
        }
        if (lane == 0) atomicAdd(&acc[2], -logf(pos / (sum - pos)));
    }
    for (int j = w; j < GG; j += 8) {
        float d = 0.f;
#pragma unroll
        for (int q = 0; q < 8; q++) {
            int c = lane + q * 32;
            d += ri[c] * semb[(size_t)j * DD + c];
        }
        d = warp_sum(d);
        if (lane == 0) dsout[(size_t)i * GG + j] = d / (ni * gnorm[j]);
    }
    __syncthreads();
    if (tid == 0) {
        __threadfence();
        int t = atomicAdd(done, 1);
        if (t == GG - 1) {
            __threadfence();
            out[O_KL]  = acc[0] / (float)NN + acc[1] / (float)EE;
            out[O_NCE] = acc[2] / (float)GG;
        }
    }
}

// -------- PDL launch helper --------
template <typename... Args>
static inline void launch_pdl(void (*kern)(Args...), dim3 grid, dim3 block, Args... args) {
    cudaLaunchConfig_t cfg = {};
    cfg.gridDim = grid;
    cfg.blockDim = block;
    cfg.dynamicSmemBytes = 0;
    cudaLaunchAttribute attr[1];
    attr[0].id = cudaLaunchAttributeProgrammaticStreamSerialization;
    attr[0].val.programmaticStreamSerializationAllowed = 1;
    cfg.attrs = attr;
    cfg.numAttrs = 1;
    cudaLaunchKernelEx(&cfg, kern, args...);
}

// =====================================================================
extern "C" void kernel_launch(void* const* d_in, const int* in_sizes, int n_in,
                              void* d_out, int out_size) {
    const float* x    = (const float*)d_in[0];
    const int*   ei   = (const int*)d_in[1];
    const int*   bat  = (const int*)d_in[2];
    const float* W1   = (const float*)d_in[3];
    const float* b1   = (const float*)d_in[4];
    const float* W2   = (const float*)d_in[5];
    const float* b2   = (const float*)d_in[6];
    const float* Wm1  = (const float*)d_in[7];
    const float* bm1  = (const float*)d_in[8];
    const float* Wm2  = (const float*)d_in[9];
    const float* bm2  = (const float*)d_in[10];
    const float* prot = (const float*)d_in[11];
    float* out = (float*)d_out;

    const int* src = ei;
    const int* dst = ei + EE;

    float *agg, *h1, *h2, *hid, *pnorm, *gnorm, *contrib, *nb, *nprob, *acc;
    int *assign, *cnt, *ptr, *cursor, *csrc, *gstart, *bsum, *done;
    cudaGetSymbolAddress((void**)&agg, g_agg);
    cudaGetSymbolAddress((void**)&h1, g_h1);
    cudaGetSymbolAddress((void**)&h2, g_h2);
    cudaGetSymbolAddress((void**)&hid, g_hid);
    cudaGetSymbolAddress((void**)&pnorm, g_pnorm);
    cudaGetSymbolAddress((void**)&gnorm, g_gnorm);
    cudaGetSymbolAddress((void**)&contrib, g_contrib);
    cudaGetSymbolAddress((void**)&nb, g_nb);
    cudaGetSymbolAddress((void**)&nprob, g_nprob);
    cudaGetSymbolAddress((void**)&acc, g_acc);
    cudaGetSymbolAddress((void**)&assign, g_assign);
    cudaGetSymbolAddress((void**)&cnt, g_cnt);
    cudaGetSymbolAddress((void**)&ptr, g_ptr);
    cudaGetSymbolAddress((void**)&cursor, g_cursor);
    cudaGetSymbolAddress((void**)&csrc, g_csrc);
    cudaGetSymbolAddress((void**)&gstart, g_gstart);
    cudaGetSymbolAddress((void**)&bsum, g_bsum);
    cudaGetSymbolAddress((void**)&done, g_done);

    auto blks = [](long n, int t) { return (int)((n + t - 1) / t); };

    // ---- init + CSR build ----
    launch_pdl(init_k, dim3(SCAN_B + 2), dim3(256),
               cnt, cursor, nprob, acc, done, bat, gstart);
    launch_pdl(hist_k, dim3(blks(EE, 256)), dim3(256), dst, cnt);
    launch_pdl(scan1_k, dim3(SCAN_B), dim3(256), (const int*)cnt, ptr, bsum);
    launch_pdl(scan2_k, dim3(SCAN_B), dim3(256), ptr, (const int*)bsum);
    launch_pdl(fill_k, dim3(blks(EE, 256)), dim3(256),
               src, dst, (const int*)ptr, cursor, csrc);
    launch_pdl(protprep_k, dim3(PP), dim3(DD), prot, Wm1, contrib, pnorm);

    dim3 gg(DD / TBN, (NN + TBM - 1) / TBM);

    // ---- pass 1 ----
    launch_pdl(gather_k<INF, 0>, dim3(blks(NN, 8)), dim3(256),
               x, (const int*)ptr, (const int*)csrc, (const float*)nullptr, agg);
    launch_pdl(gemm_tc_k, gg, dim3(256),
               (const float*)agg, W1, b1, h1, NN, INF, DD,
               (const float*)nullptr, (const int*)nullptr, (const int*)nullptr,
               (float*)nullptr, (float*)nullptr, (const float*)nullptr);
    launch_pdl(gather_k<DD, 0>, dim3(blks(NN, 4)), dim3(256),
               (const float*)h1, (const int*)ptr, (const int*)csrc,
               (const float*)nullptr, agg);
    launch_pdl(gemm_tc_k, gg, dim3(256),
               (const float*)agg, W2, b2, h2, NN, DD, DD,
               (const float*)nullptr, (const int*)nullptr, (const int*)nullptr,
               out + O_NE, (float*)nullptr, (const float*)nullptr);
    launch_pdl(pool_argmax_k, dim3(GG), dim3(256),
               (const float*)h2, (const int*)gstart, prot, (const float*)pnorm, assign);

    // ---- MLP (nodeprob dot fused into GEMM epilogue; hid not written) ----
    launch_pdl(gemm_tc_k, gg, dim3(256),
               (const float*)h2, Wm1, bm1, (float*)nullptr, NN, DD, DD,
               (const float*)contrib, bat, (const int*)assign,
               (float*)nullptr, nprob, Wm2);
    launch_pdl(nprob_sig_k, dim3(SCAN_B), dim3(256),
               (const float*)nprob, bm2, nb, out + O_NB, acc);
    launch_pdl(edgebern_k, dim3(blks(EE, 256)), dim3(256),
               (const float*)nb, src, dst, out + O_EB, acc);

    // ---- pass 2 ----
    launch_pdl(gather_k<INF, 1>, dim3(blks(NN, 8)), dim3(256),
               x, (const int*)ptr, (const int*)csrc, (const float*)nb, agg);
    launch_pdl(gemm_tc_k, gg, dim3(256),
               (const float*)agg, W1, b1, h1, NN, INF, DD,
               (const float*)nullptr, (const int*)nullptr, (const int*)nullptr,
               (float*)nullptr, (float*)nullptr, (const float*)nullptr);
    launch_pdl(gather_k<DD, 2>, dim3(blks(NN, 4)), dim3(256),
               (const float*)h1, (const int*)ptr, (const int*)csrc,
               (const float*)nb, agg);
    launch_pdl(gemm_tc_k, gg, dim3(256),
               (const float*)agg, W2, b2, hid, NN, DD, DD,
               (const float*)nullptr, (const int*)nullptr, (const int*)nullptr,
               (float*)nullptr, (float*)nullptr, (const float*)nullptr);
    launch_pdl(pool_norm_k, dim3(GG), dim3(256),
               (const float*)hid, (const int*)gstart, out + O_SE, gnorm);

    // ---- similarity / NCE / data_sim / finalize ----
    launch_pdl(simdata_k, dim3(GG), dim3(DD),
               (const float*)(out + O_SE), (const float*)gnorm, prot,
               (const float*)pnorm, out + O_SIM, out + O_DS, acc, done, out);
}